// round 11
// baseline (speedup 1.0000x reference)
#include <cuda_runtime.h>
#include <cuda_fp16.h>
#include <cstdint>
#include <cstddef>

#define B_   4
#define T_   448
#define TPAD 512
#define U_   448
#define SKS_ 96
#define BKS_ 32
#define H_   96
#define V_   128
#define PITCH 208          // smem row pitch (96 fp16 = 192 B + pad) -> conflict-free ldmatrix
#define SPITCH 272         // staging row pitch (256 B half-row + 16) -> <=2-way STS conflicts

// ---------------- device scratch (fp16) ----------------
__device__ __align__(16) unsigned short g_shh [B_ * TPAD * H_];  // fp16 sh
__device__ __align__(16) unsigned short g_rbhh[B_ * U_ * H_];    // fp16 relu(bh)

// ---------------- asm helpers ----------------
__device__ __forceinline__ uint32_t smem_u32(const void* p) {
    uint32_t a;
    asm("{ .reg .u64 t; cvta.to.shared.u64 t, %1; cvt.u32.u64 %0, t; }" : "=r"(a) : "l"(p));
    return a;
}
#define LDSM4(r, addr) \
    asm volatile("ldmatrix.sync.aligned.m8n8.x4.shared.b16 {%0,%1,%2,%3}, [%4];" \
        : "=r"((r)[0]), "=r"((r)[1]), "=r"((r)[2]), "=r"((r)[3]) : "r"(addr))

#define MMA16816(c, a0, a1, a2, a3, b0, b1) \
    asm volatile("mma.sync.aligned.m16n8k16.row.col.f32.f16.f16.f32 " \
        "{%0,%1,%2,%3}, {%4,%5,%6,%7}, {%8,%9}, {%0,%1,%2,%3};" \
        : "+f"((c)[0]), "+f"((c)[1]), "+f"((c)[2]), "+f"((c)[3]) \
        : "r"(a0), "r"(a1), "r"(a2), "r"(a3), "r"(b0), "r"(b1))

__device__ __forceinline__ uint32_t hmul2u(uint32_t a, uint32_t b) {
    __half2 r = __hmul2(*reinterpret_cast<__half2*>(&a), *reinterpret_cast<__half2*>(&b));
    return *reinterpret_cast<uint32_t*>(&r);
}

// ============================================================================
// Input projections; outputs stored as fp16. (unchanged from R10)
// ============================================================================
__global__ __launch_bounds__(96) void proj8(
    const float* __restrict__ s,   const float* __restrict__ bmat,
    const float* __restrict__ Wsh, const float* __restrict__ bsh,
    const float* __restrict__ Wbh, const float* __restrict__ bbh)
{
    __shared__ float sw[H_ * 97];
    __shared__ float srow[8][97];
    const int h = threadIdx.x;

    if (blockIdx.y == 0) {
        for (int i = h; i < H_ * SKS_; i += 96)
            sw[(i / SKS_) * 97 + (i % SKS_)] = Wsh[i];
        const int base = blockIdx.x * 8;
        #pragma unroll
        for (int r = 0; r < 8; r++) {
            int row = base + r, b = row >> 9, t = row & 511;
            srow[r][h] = (t < T_) ? s[((size_t)b * T_ + t) * SKS_ + h] : 0.0f;
        }
        __syncthreads();
        float acc[8];
        const float bias = bsh[h];
        #pragma unroll
        for (int r = 0; r < 8; r++) acc[r] = bias;
        #pragma unroll 4
        for (int k = 0; k < SKS_; k++) {
            float w = sw[h * 97 + k];
            #pragma unroll
            for (int r = 0; r < 8; r++) acc[r] = fmaf(srow[r][k], w, acc[r]);
        }
        #pragma unroll
        for (int r = 0; r < 8; r++) {
            __half v = __float2half_rn(acc[r]);
            g_shh[(size_t)(base + r) * H_ + h] = *reinterpret_cast<unsigned short*>(&v);
        }
    } else {
        if (blockIdx.x >= (B_ * U_) / 8) return;
        for (int i = h; i < H_ * BKS_; i += 96)
            sw[(i / BKS_) * 33 + (i % BKS_)] = Wbh[i];
        const int base = blockIdx.x * 8;
        if (h < BKS_) {
            #pragma unroll
            for (int r = 0; r < 8; r++)
                srow[r][h] = bmat[(size_t)(base + r) * BKS_ + h];
        }
        __syncthreads();
        float acc[8];
        const float bias = bbh[h];
        #pragma unroll
        for (int r = 0; r < 8; r++) acc[r] = bias;
        #pragma unroll
        for (int k = 0; k < BKS_; k++) {
            float w = sw[h * 33 + k];
            #pragma unroll
            for (int r = 0; r < 8; r++) acc[r] = fmaf(srow[r][k], w, acc[r]);
        }
        #pragma unroll
        for (int r = 0; r < 8; r++) {
            __half v = __float2half_rn(fmaxf(acc[r], 0.0f));
            g_rbhh[(size_t)(base + r) * H_ + h] = *reinterpret_cast<unsigned short*>(&v);
        }
    }
}

// ============================================================================
// Main kernel (R10 body + async bulk stores).
// grid (18, 16): y = (bz, t0) group, x = u-chunk (~25 u's).
// Epilogue: lse-subtract in regs -> STS to staging (2 half-row phases) ->
// cp.async.bulk 256B row copies (full-line async writes, no STG wavefronts).
// ============================================================================
#define S_BH   0                    // [128][PITCH] fp16 W
#define S_SHH  26624                // [128][PITCH] fp16 sh tile
#define S_RED  53248                // [128][2] float2
#define S_RBH  55296                // [2][48] uint (half2 rbh)
#define S_BIA  55680                // [128] float
#define S_STG  56192                // [128][SPITCH] staging (one 256B half-row per phase)
#define SMEM_MAIN 91008

__global__ __launch_bounds__(256, 2) void joiner_hmma(
    const float* __restrict__ Wout, const float* __restrict__ bout,
    float* __restrict__ out)
{
    extern __shared__ __align__(16) char smem[];
    const uint32_t sb = smem_u32(smem);
    const int tid = threadIdx.x;
    const int wid = tid >> 5, lid = tid & 31;
    const int mg = wid >> 1, ng = wid & 1;
    const int n0 = ng * 64;
    const int q  = lid >> 2, qe = lid & 3;

    const int g  = blockIdx.y;
    const int t0 = (g & 3) * 128;
    const int bz = g >> 2;
    const int c  = blockIdx.x;                       // 0..17
    const int ustart = c * 24 + (c < 16 ? c : 16);
    const int ucnt   = 24 + (c < 16 ? 1 : 0);

    // ---- one-time: stage W (fp16), bias, sh fp16 tile ----
    for (int idx = tid; idx < V_ * H_; idx += 256) {
        const int n = idx / H_, k = idx - n * H_;
        *(__half*)(smem + S_BH + n * PITCH + k * 2) = __float2half_rn(Wout[idx]);
    }
    if (tid < V_) ((float*)(smem + S_BIA))[tid] = bout[tid];
    {
        const uint4* src = (const uint4*)(g_shh + ((size_t)(bz * TPAD) + t0) * H_);
        for (int i = tid; i < 128 * 12; i += 256) {
            const int row = i / 12, kq = i - row * 12;
            *(uint4*)(smem + S_SHH + row * PITCH + kq * 16) = src[row * 12 + kq];
        }
    }

    // ldmatrix lane addresses
    const uint32_t aoff = (uint32_t)((lid & 15) * PITCH + (lid >> 4) * 16);
    const uint32_t boff = (uint32_t)(((lid & 7) + ((lid >> 4) << 3)) * PITCH + ((lid >> 3) & 1) * 16);
    const uint32_t sAh = sb + S_SHH + (uint32_t)(mg * 32 * PITCH) + aoff;
    const uint32_t sBh = sb + S_BH + (uint32_t)(n0 * PITCH) + boff;

    float2*   red   = (float2*)(smem + S_RED);
    uint32_t* rbAll = (uint32_t*)(smem + S_RBH);
    const float* biaL = (const float*)(smem + S_BIA) + n0 + 2 * qe;

    // copy-thread state (tid < 128: one output row each)
    const int rowt = t0 + tid;
    const bool cvalid = (tid < 128) && (rowt < T_);
    const uint32_t stgAddr = sb + S_STG + (uint32_t)(tid * SPITCH);
    char* stg = smem + S_STG;

    // prologue: rbh for first item into buffer 0
    if (tid < 48)
        rbAll[tid] = ((const uint32_t*)(g_rbhh + ((size_t)bz * U_ + ustart) * H_))[tid];

    int p = 0;
    for (int it = 0; it < ucnt; it++, p ^= 1) {
        const int u = ustart + it;

        // staging free (previous item's phase-B reads done) + rbh buffer ready
        if (tid < 128) asm volatile("cp.async.bulk.wait_group.read 0;" ::: "memory");
        __syncthreads();

        // prefetch next item's rbh (half2)
        uint32_t nrb = 0u;
        if (tid < 48 && it + 1 < ucnt)
            nrb = ((const uint32_t*)(g_rbhh + ((size_t)bz * U_ + u + 1) * H_))[tid];

        const char* rbB = (const char*)(rbAll + p * 48);

        float acc[2][8][4];
        #pragma unroll
        for (int i = 0; i < 2; i++)
            #pragma unroll
            for (int j = 0; j < 8; j++)
                #pragma unroll
                for (int e4 = 0; e4 < 4; e4++) acc[i][j][e4] = 0.0f;

        // ---- 6 k-steps: A = LDSM(sh) * rbh (HMUL2), B via LDSM ----
        #pragma unroll
        for (int s = 0; s < 6; s++) {
            uint32_t rb0 = *(const uint32_t*)(rbB + s * 32 + qe * 4);
            uint32_t rb1 = *(const uint32_t*)(rbB + s * 32 + 16 + qe * 4);
            uint32_t am[2][4], ah[2][4], bq[4][4];
            #pragma unroll
            for (int i = 0; i < 2; i++) {
                LDSM4(am[i], sAh + i * 16 * PITCH + s * 32);
                ah[i][0] = hmul2u(am[i][0], rb0);
                ah[i][1] = hmul2u(am[i][1], rb0);
                ah[i][2] = hmul2u(am[i][2], rb1);
                ah[i][3] = hmul2u(am[i][3], rb1);
            }
            #pragma unroll
            for (int jj = 0; jj < 4; jj++)
                LDSM4(bq[jj], sBh + jj * 16 * PITCH + s * 32);
            #pragma unroll
            for (int i = 0; i < 2; i++)
                #pragma unroll
                for (int j = 0; j < 8; j++)
                    MMA16816(acc[i][j], ah[i][0], ah[i][1], ah[i][2], ah[i][3],
                             bq[j >> 1][(j & 1) * 2], bq[j >> 1][(j & 1) * 2 + 1]);
        }

        // park next rbh into the other buffer
        if (tid < 48 && it + 1 < ucnt) rbAll[(p ^ 1) * 48 + tid] = nrb;

        // ---- bias add ----
        #pragma unroll
        for (int j = 0; j < 8; j++) {
            float2 bv = *(const float2*)(biaL + 8 * j);
            #pragma unroll
            for (int i = 0; i < 2; i++) {
                acc[i][j][0] += bv.x; acc[i][j][1] += bv.y;
                acc[i][j][2] += bv.x; acc[i][j][3] += bv.y;
            }
        }

        // ---- log-softmax partials + cross-warp exchange ----
        float mx[2][2], sm[2][2];
        #pragma unroll
        for (int i = 0; i < 2; i++)
            #pragma unroll
            for (int h = 0; h < 2; h++) {
                float m = -3.4e38f;
                #pragma unroll
                for (int j = 0; j < 8; j++) {
                    m = fmaxf(m, acc[i][j][2 * h]);
                    m = fmaxf(m, acc[i][j][2 * h + 1]);
                }
                m = fmaxf(m, __shfl_xor_sync(0xffffffffu, m, 1));
                m = fmaxf(m, __shfl_xor_sync(0xffffffffu, m, 2));
                float ss = 0.0f;
                #pragma unroll
                for (int j = 0; j < 8; j++)
                    ss += __expf(acc[i][j][2 * h] - m) + __expf(acc[i][j][2 * h + 1] - m);
                ss += __shfl_xor_sync(0xffffffffu, ss, 1);
                ss += __shfl_xor_sync(0xffffffffu, ss, 2);
                mx[i][h] = m; sm[i][h] = ss;
            }
        if (qe == 0) {
            #pragma unroll
            for (int i = 0; i < 2; i++)
                #pragma unroll
                for (int h = 0; h < 2; h++)
                    red[(mg * 32 + i * 16 + h * 8 + q) * 2 + ng] = make_float2(mx[i][h], sm[i][h]);
        }
        __syncthreads();

        // finalize lse per (i,h)
        float lse[2][2];
        #pragma unroll
        for (int i = 0; i < 2; i++)
            #pragma unroll
            for (int h = 0; h < 2; h++) {
                float2 o = red[(mg * 32 + i * 16 + h * 8 + q) * 2 + (ng ^ 1)];
                float M = fmaxf(mx[i][h], o.x);
                float S = sm[i][h] * __expf(mx[i][h] - M) + o.y * __expf(o.x - M);
                lse[i][h] = M + __logf(S);
            }

        const char* gRow = (const char*)(out + (((size_t)bz * T_ + rowt) * U_ + u) * V_);

        // ---- phase A: ng==0 warps stage cols 0..63; async copy half 0 ----
        if (ng == 0) {
            #pragma unroll
            for (int i = 0; i < 2; i++)
                #pragma unroll
                for (int h = 0; h < 2; h++) {
                    char* rowp = stg + (mg * 32 + i * 16 + h * 8 + q) * SPITCH + qe * 8;
                    const float l = lse[i][h];
                    #pragma unroll
                    for (int j = 0; j < 8; j++)
                        *(float2*)(rowp + j * 32) =
                            make_float2(acc[i][j][2 * h] - l, acc[i][j][2 * h + 1] - l);
                }
        }
        __syncthreads();
        if (cvalid) {
            asm volatile("fence.proxy.async.shared::cta;" ::: "memory");
            asm volatile("cp.async.bulk.global.shared::cta.bulk_group [%0], [%1], %2;"
                :: "l"(gRow), "r"(stgAddr), "r"(256u) : "memory");
            asm volatile("cp.async.bulk.commit_group;" ::: "memory");
        }
        if (tid < 128) asm volatile("cp.async.bulk.wait_group.read 0;" ::: "memory");
        __syncthreads();

        // ---- phase B: ng==1 warps stage cols 64..127; async copy half 1 ----
        if (ng == 1) {
            #pragma unroll
            for (int i = 0; i < 2; i++)
                #pragma unroll
                for (int h = 0; h < 2; h++) {
                    char* rowp = stg + (mg * 32 + i * 16 + h * 8 + q) * SPITCH + qe * 8;
                    const float l = lse[i][h];
                    #pragma unroll
                    for (int j = 0; j < 8; j++)
                        *(float2*)(rowp + j * 32) =
                            make_float2(acc[i][j][2 * h] - l, acc[i][j][2 * h + 1] - l);
                }
        }
        __syncthreads();
        if (cvalid) {
            asm volatile("fence.proxy.async.shared::cta;" ::: "memory");
            asm volatile("cp.async.bulk.global.shared::cta.bulk_group [%0], [%1], %2;"
                :: "l"(gRow + 256), "r"(stgAddr), "r"(256u) : "memory");
            asm volatile("cp.async.bulk.commit_group;" ::: "memory");
        }
        // reads for phase B are awaited at the top of the next iteration
    }
}

extern "C" void kernel_launch(void* const* d_in, const int* in_sizes, int n_in,
                              void* d_out, int out_size)
{
    (void)in_sizes; (void)n_in; (void)out_size;
    const float* s    = (const float*)d_in[0];
    const float* bmat = (const float*)d_in[1];
    const float* Wsh  = (const float*)d_in[2];
    const float* bsh  = (const float*)d_in[3];
    const float* Wbh  = (const float*)d_in[4];
    const float* bbh  = (const float*)d_in[5];
    const float* Wout = (const float*)d_in[6];
    const float* bout = (const float*)d_in[7];
    float* out = (float*)d_out;

    cudaFuncSetAttribute(joiner_hmma,
                         cudaFuncAttributeMaxDynamicSharedMemorySize, SMEM_MAIN);

    proj8<<<dim3((B_ * TPAD) / 8, 2), 96>>>(s, bmat, Wsh, bsh, Wbh, bbh);
    joiner_hmma<<<dim3(18, 16), 256, SMEM_MAIN>>>(Wout, bout, out);
}

// round 12
// speedup vs baseline: 1.2252x; 1.2252x over previous
#include <cuda_runtime.h>
#include <cuda_fp16.h>
#include <cstdint>
#include <cstddef>

#define B_   4
#define T_   448
#define TPAD 512
#define U_   448
#define SKS_ 96
#define BKS_ 32
#define H_   96
#define V_   128
#define PITCH 208          // smem row pitch (96 fp16 = 192 B + pad) -> conflict-free ldmatrix

// ---------------- device scratch (fp16) ----------------
__device__ __align__(16) unsigned short g_shh [B_ * TPAD * H_];  // fp16 sh
__device__ __align__(16) unsigned short g_rbhh[B_ * U_ * H_];    // fp16 relu(bh)

// ---------------- asm helpers ----------------
__device__ __forceinline__ uint32_t smem_u32(const void* p) {
    uint32_t a;
    asm("{ .reg .u64 t; cvta.to.shared.u64 t, %1; cvt.u32.u64 %0, t; }" : "=r"(a) : "l"(p));
    return a;
}
#define LDSM4(r, addr) \
    asm volatile("ldmatrix.sync.aligned.m8n8.x4.shared.b16 {%0,%1,%2,%3}, [%4];" \
        : "=r"((r)[0]), "=r"((r)[1]), "=r"((r)[2]), "=r"((r)[3]) : "r"(addr))

#define MMA16816(c, a0, a1, a2, a3, b0, b1) \
    asm volatile("mma.sync.aligned.m16n8k16.row.col.f32.f16.f16.f32 " \
        "{%0,%1,%2,%3}, {%4,%5,%6,%7}, {%8,%9}, {%0,%1,%2,%3};" \
        : "+f"((c)[0]), "+f"((c)[1]), "+f"((c)[2]), "+f"((c)[3]) \
        : "r"(a0), "r"(a1), "r"(a2), "r"(a3), "r"(b0), "r"(b1))

__device__ __forceinline__ uint32_t hmul2u(uint32_t a, uint32_t b) {
    __half2 r = __hmul2(*reinterpret_cast<__half2*>(&a), *reinterpret_cast<__half2*>(&b));
    return *reinterpret_cast<uint32_t*>(&r);
}

// Column permutation: physical slot p (within a 64-col half) -> logical col.
// phys p = 8*j + 2*qe + e  maps to  L = 16*(j>>1) + 4*qe + 2*(j&1) + e.
// Inverse (logical v -> phys p), used when staging W and bias:
__device__ __forceinline__ int perm_phys(int v) {
    const int m = v >> 4, r = v & 15;
    const int qe = r >> 2, rem = r & 3;
    const int j = 2 * m + (rem >> 1), e = rem & 1;
    return 8 * j + 2 * qe + e;
}

// ============================================================================
// Input projections; outputs stored as fp16. (unchanged from R10)
// ============================================================================
__global__ __launch_bounds__(96) void proj8(
    const float* __restrict__ s,   const float* __restrict__ bmat,
    const float* __restrict__ Wsh, const float* __restrict__ bsh,
    const float* __restrict__ Wbh, const float* __restrict__ bbh)
{
    __shared__ float sw[H_ * 97];
    __shared__ float srow[8][97];
    const int h = threadIdx.x;

    if (blockIdx.y == 0) {
        for (int i = h; i < H_ * SKS_; i += 96)
            sw[(i / SKS_) * 97 + (i % SKS_)] = Wsh[i];
        const int base = blockIdx.x * 8;
        #pragma unroll
        for (int r = 0; r < 8; r++) {
            int row = base + r, b = row >> 9, t = row & 511;
            srow[r][h] = (t < T_) ? s[((size_t)b * T_ + t) * SKS_ + h] : 0.0f;
        }
        __syncthreads();
        float acc[8];
        const float bias = bsh[h];
        #pragma unroll
        for (int r = 0; r < 8; r++) acc[r] = bias;
        #pragma unroll 4
        for (int k = 0; k < SKS_; k++) {
            float w = sw[h * 97 + k];
            #pragma unroll
            for (int r = 0; r < 8; r++) acc[r] = fmaf(srow[r][k], w, acc[r]);
        }
        #pragma unroll
        for (int r = 0; r < 8; r++) {
            __half v = __float2half_rn(acc[r]);
            g_shh[(size_t)(base + r) * H_ + h] = *reinterpret_cast<unsigned short*>(&v);
        }
    } else {
        if (blockIdx.x >= (B_ * U_) / 8) return;
        for (int i = h; i < H_ * BKS_; i += 96)
            sw[(i / BKS_) * 33 + (i % BKS_)] = Wbh[i];
        const int base = blockIdx.x * 8;
        if (h < BKS_) {
            #pragma unroll
            for (int r = 0; r < 8; r++)
                srow[r][h] = bmat[(size_t)(base + r) * BKS_ + h];
        }
        __syncthreads();
        float acc[8];
        const float bias = bbh[h];
        #pragma unroll
        for (int r = 0; r < 8; r++) acc[r] = bias;
        #pragma unroll
        for (int k = 0; k < BKS_; k++) {
            float w = sw[h * 33 + k];
            #pragma unroll
            for (int r = 0; r < 8; r++) acc[r] = fmaf(srow[r][k], w, acc[r]);
        }
        #pragma unroll
        for (int r = 0; r < 8; r++) {
            __half v = __float2half_rn(fmaxf(acc[r], 0.0f));
            g_rbhh[(size_t)(base + r) * H_ + h] = *reinterpret_cast<unsigned short*>(&v);
        }
    }
}

// ============================================================================
// Main kernel (R10 body + permuted B columns -> float4 STG.128 stores).
// grid (18, 16): y = (bz, t0) group, x = u-chunk (~25 u's).
// ============================================================================
#define S_BH   0                    // [128][PITCH] fp16 W (rows permuted)
#define S_SHH  26624                // [128][PITCH] fp16 sh tile
#define S_RED  53248                // [128][2] float2
#define S_RBH  55296                // [2][48] uint (half2 rbh)
#define S_BIA  55680                // [128] float (permuted)
#define SMEM_MAIN 56192

__global__ __launch_bounds__(256, 2) void joiner_hmma(
    const float* __restrict__ Wout, const float* __restrict__ bout,
    float* __restrict__ out)
{
    extern __shared__ __align__(16) char smem[];
    const uint32_t sb = smem_u32(smem);
    const int tid = threadIdx.x;
    const int wid = tid >> 5, lid = tid & 31;
    const int mg = wid >> 1, ng = wid & 1;
    const int n0 = ng * 64;
    const int q  = lid >> 2, qe = lid & 3;

    const int g  = blockIdx.y;
    const int t0 = (g & 3) * 128;
    const int bz = g >> 2;
    const int c  = blockIdx.x;                       // 0..17
    const int ustart = c * 24 + (c < 16 ? c : 16);
    const int ucnt   = 24 + (c < 16 ? 1 : 0);

    // ---- one-time: stage W fp16 (rows PERMUTED), bias (permuted), sh tile ----
    for (int idx = tid; idx < V_ * H_; idx += 256) {
        const int n = idx / H_, k = idx - n * H_;
        const int p = (n & 64) + perm_phys(n & 63);
        *(__half*)(smem + S_BH + p * PITCH + k * 2) = __float2half_rn(Wout[idx]);
    }
    if (tid < V_) {
        const int p = (tid & 64) + perm_phys(tid & 63);
        ((float*)(smem + S_BIA))[p] = bout[tid];
    }
    {
        const uint4* src = (const uint4*)(g_shh + ((size_t)(bz * TPAD) + t0) * H_);
        for (int i = tid; i < 128 * 12; i += 256) {
            const int row = i / 12, kq = i - row * 12;
            *(uint4*)(smem + S_SHH + row * PITCH + kq * 16) = src[row * 12 + kq];
        }
    }

    // ldmatrix lane addresses
    const uint32_t aoff = (uint32_t)((lid & 15) * PITCH + (lid >> 4) * 16);
    const uint32_t boff = (uint32_t)(((lid & 7) + ((lid >> 4) << 3)) * PITCH + ((lid >> 3) & 1) * 16);
    const uint32_t sAh = sb + S_SHH + (uint32_t)(mg * 32 * PITCH) + aoff;
    const uint32_t sBh = sb + S_BH + (uint32_t)(n0 * PITCH) + boff;

    float2*   red   = (float2*)(smem + S_RED);
    uint32_t* rbAll = (uint32_t*)(smem + S_RBH);     // [2][48] half2
    const float* biaL = (const float*)(smem + S_BIA) + n0 + 2 * qe;   // phys-indexed

    // prologue: rbh for first item into buffer 0
    if (tid < 48)
        rbAll[tid] = ((const uint32_t*)(g_rbhh + ((size_t)bz * U_ + ustart) * H_))[tid];

    int p = 0;
    for (int it = 0; it < ucnt; it++, p ^= 1) {
        const int u = ustart + it;

        __syncthreads();   // rbh buffer p + tiles ready; prev red consumed

        // prefetch next item's rbh (half2) into a register
        uint32_t nrb = 0u;
        if (tid < 48 && it + 1 < ucnt)
            nrb = ((const uint32_t*)(g_rbhh + ((size_t)bz * U_ + u + 1) * H_))[tid];

        const char* rbB = (const char*)(rbAll + p * 48);

        float acc[2][8][4];
        #pragma unroll
        for (int i = 0; i < 2; i++)
            #pragma unroll
            for (int j = 0; j < 8; j++)
                #pragma unroll
                for (int e4 = 0; e4 < 4; e4++) acc[i][j][e4] = 0.0f;

        // ---- 6 k-steps: A = LDSM(sh) * rbh (HMUL2), B via LDSM ----
        #pragma unroll
        for (int s = 0; s < 6; s++) {
            uint32_t rb0 = *(const uint32_t*)(rbB + s * 32 + qe * 4);
            uint32_t rb1 = *(const uint32_t*)(rbB + s * 32 + 16 + qe * 4);
            uint32_t am[2][4], ah[2][4], bq[4][4];
            #pragma unroll
            for (int i = 0; i < 2; i++) {
                LDSM4(am[i], sAh + i * 16 * PITCH + s * 32);
                ah[i][0] = hmul2u(am[i][0], rb0);
                ah[i][1] = hmul2u(am[i][1], rb0);
                ah[i][2] = hmul2u(am[i][2], rb1);
                ah[i][3] = hmul2u(am[i][3], rb1);
            }
            #pragma unroll
            for (int jj = 0; jj < 4; jj++)
                LDSM4(bq[jj], sBh + jj * 16 * PITCH + s * 32);
            #pragma unroll
            for (int i = 0; i < 2; i++)
                #pragma unroll
                for (int j = 0; j < 8; j++)
                    MMA16816(acc[i][j], ah[i][0], ah[i][1], ah[i][2], ah[i][3],
                             bq[j >> 1][(j & 1) * 2], bq[j >> 1][(j & 1) * 2 + 1]);
        }

        // park next rbh into the other buffer
        if (tid < 48 && it + 1 < ucnt) rbAll[(p ^ 1) * 48 + tid] = nrb;

        // ---- bias add (phys-indexed permuted bias) ----
        #pragma unroll
        for (int j = 0; j < 8; j++) {
            float2 bv = *(const float2*)(biaL + 8 * j);
            #pragma unroll
            for (int i = 0; i < 2; i++) {
                acc[i][j][0] += bv.x; acc[i][j][1] += bv.y;
                acc[i][j][2] += bv.x; acc[i][j][3] += bv.y;
            }
        }

        // ---- epilogue: log-softmax over V=128 (two warps share each row) ----
        float mx[2][2], sm[2][2];
        #pragma unroll
        for (int i = 0; i < 2; i++)
            #pragma unroll
            for (int h = 0; h < 2; h++) {
                float m = -3.4e38f;
                #pragma unroll
                for (int j = 0; j < 8; j++) {
                    m = fmaxf(m, acc[i][j][2 * h]);
                    m = fmaxf(m, acc[i][j][2 * h + 1]);
                }
                m = fmaxf(m, __shfl_xor_sync(0xffffffffu, m, 1));
                m = fmaxf(m, __shfl_xor_sync(0xffffffffu, m, 2));
                float ss = 0.0f;
                #pragma unroll
                for (int j = 0; j < 8; j++)
                    ss += __expf(acc[i][j][2 * h] - m) + __expf(acc[i][j][2 * h + 1] - m);
                ss += __shfl_xor_sync(0xffffffffu, ss, 1);
                ss += __shfl_xor_sync(0xffffffffu, ss, 2);
                mx[i][h] = m; sm[i][h] = ss;
            }
        if (qe == 0) {
            #pragma unroll
            for (int i = 0; i < 2; i++)
                #pragma unroll
                for (int h = 0; h < 2; h++)
                    red[(mg * 32 + i * 16 + h * 8 + q) * 2 + ng] = make_float2(mx[i][h], sm[i][h]);
        }
        __syncthreads();

        // ---- store: permutation makes each lane own 4 consecutive cols ----
        #pragma unroll
        for (int i = 0; i < 2; i++)
            #pragma unroll
            for (int h = 0; h < 2; h++) {
                const int rloc = i * 16 + h * 8 + q;
                const int t = t0 + mg * 32 + rloc;
                if (t >= T_) continue;
                float2 o = red[(mg * 32 + rloc) * 2 + (ng ^ 1)];
                float M = fmaxf(mx[i][h], o.x);
                float S = sm[i][h] * __expf(mx[i][h] - M) + o.y * __expf(o.x - M);
                float lse = M + __logf(S);
                float* orow = out + (((size_t)bz * T_ + t) * U_ + u) * V_ + n0 + 4 * qe;
                #pragma unroll
                for (int m2 = 0; m2 < 4; m2++) {
                    float4 v;
                    v.x = acc[i][2 * m2][2 * h]         - lse;
                    v.y = acc[i][2 * m2][2 * h + 1]     - lse;
                    v.z = acc[i][2 * m2 + 1][2 * h]     - lse;
                    v.w = acc[i][2 * m2 + 1][2 * h + 1] - lse;
                    *(float4*)(orow + 16 * m2) = v;
                }
            }
    }
}

extern "C" void kernel_launch(void* const* d_in, const int* in_sizes, int n_in,
                              void* d_out, int out_size)
{
    (void)in_sizes; (void)n_in; (void)out_size;
    const float* s    = (const float*)d_in[0];
    const float* bmat = (const float*)d_in[1];
    const float* Wsh  = (const float*)d_in[2];
    const float* bsh  = (const float*)d_in[3];
    const float* Wbh  = (const float*)d_in[4];
    const float* bbh  = (const float*)d_in[5];
    const float* Wout = (const float*)d_in[6];
    const float* bout = (const float*)d_in[7];
    float* out = (float*)d_out;

    cudaFuncSetAttribute(joiner_hmma,
                         cudaFuncAttributeMaxDynamicSharedMemorySize, SMEM_MAIN);

    proj8<<<dim3((B_ * TPAD) / 8, 2), 96>>>(s, bmat, Wsh, bsh, Wbh, bbh);
    joiner_hmma<<<dim3(18, 16), 256, SMEM_MAIN>>>(Wout, bout, out);
}

// round 14
// speedup vs baseline: 1.3002x; 1.0612x over previous
#include <cuda_runtime.h>
#include <cuda_fp16.h>
#include <cstdint>
#include <cstddef>

#define B_   4
#define T_   448
#define TPAD 512
#define U_   448
#define SKS_ 96
#define BKS_ 32
#define H_   96
#define V_   128
#define PITCH 208          // smem row pitch (96 fp16 = 192 B + pad) -> conflict-free ldmatrix
#define LOG2E 1.4426950408889634f
#define LN2   0.6931471805599453f

// ---------------- device scratch (fp16) ----------------
__device__ __align__(16) unsigned short g_shh [B_ * TPAD * H_];  // fp16 sh
__device__ __align__(16) unsigned short g_rbhh[B_ * U_ * H_];    // fp16 relu(bh)

// ---------------- asm helpers ----------------
__device__ __forceinline__ uint32_t smem_u32(const void* p) {
    uint32_t a;
    asm("{ .reg .u64 t; cvta.to.shared.u64 t, %1; cvt.u32.u64 %0, t; }" : "=r"(a) : "l"(p));
    return a;
}
__device__ __forceinline__ float ex2f(float x) {
    float r;
    asm("ex2.approx.ftz.f32 %0, %1;" : "=f"(r) : "f"(x));
    return r;
}
#define LDSM4(r, addr) \
    asm volatile("ldmatrix.sync.aligned.m8n8.x4.shared.b16 {%0,%1,%2,%3}, [%4];" \
        : "=r"((r)[0]), "=r"((r)[1]), "=r"((r)[2]), "=r"((r)[3]) : "r"(addr))

#define MMA16816(c, a0, a1, a2, a3, b0, b1) \
    asm volatile("mma.sync.aligned.m16n8k16.row.col.f32.f16.f16.f32 " \
        "{%0,%1,%2,%3}, {%4,%5,%6,%7}, {%8,%9}, {%0,%1,%2,%3};" \
        : "+f"((c)[0]), "+f"((c)[1]), "+f"((c)[2]), "+f"((c)[3]) \
        : "r"(a0), "r"(a1), "r"(a2), "r"(a3), "r"(b0), "r"(b1))

__device__ __forceinline__ uint32_t hmul2u(uint32_t a, uint32_t b) {
    __half2 r = __hmul2(*reinterpret_cast<__half2*>(&a), *reinterpret_cast<__half2*>(&b));
    return *reinterpret_cast<uint32_t*>(&r);
}

// Column permutation over the full 128 cols:
// phys slot p = 8*j + 2*qe + e  (j in [0,16))  holds logical col
//   L = 16*(j>>1) + 4*qe + 2*(j&1) + e
// so lane qe's register quad (acc[2m], acc[2m+1]) is 4 consecutive logical
// cols at 16*m + 4*qe  ->  STG.128. Inverse (logical v -> phys p):
__device__ __forceinline__ int perm_phys(int v) {
    return 16 * (v >> 4) + 8 * ((v & 3) >> 1) + 2 * ((v >> 2) & 3) + (v & 1);
}

// ============================================================================
// Input projections; outputs stored as fp16. (unchanged)
// ============================================================================
__global__ __launch_bounds__(96) void proj8(
    const float* __restrict__ s,   const float* __restrict__ bmat,
    const float* __restrict__ Wsh, const float* __restrict__ bsh,
    const float* __restrict__ Wbh, const float* __restrict__ bbh)
{
    __shared__ float sw[H_ * 97];
    __shared__ float srow[8][97];
    const int h = threadIdx.x;

    if (blockIdx.y == 0) {
        for (int i = h; i < H_ * SKS_; i += 96)
            sw[(i / SKS_) * 97 + (i % SKS_)] = Wsh[i];
        const int base = blockIdx.x * 8;
        #pragma unroll
        for (int r = 0; r < 8; r++) {
            int row = base + r, b = row >> 9, t = row & 511;
            srow[r][h] = (t < T_) ? s[((size_t)b * T_ + t) * SKS_ + h] : 0.0f;
        }
        __syncthreads();
        float acc[8];
        const float bias = bsh[h];
        #pragma unroll
        for (int r = 0; r < 8; r++) acc[r] = bias;
        #pragma unroll 4
        for (int k = 0; k < SKS_; k++) {
            float w = sw[h * 97 + k];
            #pragma unroll
            for (int r = 0; r < 8; r++) acc[r] = fmaf(srow[r][k], w, acc[r]);
        }
        #pragma unroll
        for (int r = 0; r < 8; r++) {
            __half v = __float2half_rn(acc[r]);
            g_shh[(size_t)(base + r) * H_ + h] = *reinterpret_cast<unsigned short*>(&v);
        }
    } else {
        if (blockIdx.x >= (B_ * U_) / 8) return;
        for (int i = h; i < H_ * BKS_; i += 96)
            sw[(i / BKS_) * 33 + (i % BKS_)] = Wbh[i];
        const int base = blockIdx.x * 8;
        if (h < BKS_) {
            #pragma unroll
            for (int r = 0; r < 8; r++)
                srow[r][h] = bmat[(size_t)(base + r) * BKS_ + h];
        }
        __syncthreads();
        float acc[8];
        const float bias = bbh[h];
        #pragma unroll
        for (int r = 0; r < 8; r++) acc[r] = bias;
        #pragma unroll
        for (int k = 0; k < BKS_; k++) {
            float w = sw[h * 33 + k];
            #pragma unroll
            for (int r = 0; r < 8; r++) acc[r] = fmaf(srow[r][k], w, acc[r]);
        }
        #pragma unroll
        for (int r = 0; r < 8; r++) {
            __half v = __float2half_rn(fmaxf(acc[r], 0.0f));
            g_rbhh[(size_t)(base + r) * H_ + h] = *reinterpret_cast<unsigned short*>(&v);
        }
    }
}

// ============================================================================
// Main kernel. grid (18, 16): y = (bz, t0) group, x = u-chunk (~25 u's).
// Warp layout: mg = wid (8 warps), each warp owns rows mg*16..+15 and ALL
// 128 cols -> warp-local log-softmax (no cross-warp exchange, 1 barrier/item).
// W and bias staged scaled by log2(e) -> exp via bare MUFU ex2; output FFMA.
// ============================================================================
#define S_BH   0                    // [128][PITCH] fp16 W*log2e (rows permuted)
#define S_SHH  26624                // [128][PITCH] fp16 sh tile
#define S_RBH  53248                // [2][48] uint (half2 rbh)
#define S_BIA  53632                // [128] float bias*log2e (permuted)
#define SMEM_MAIN 54272

__global__ __launch_bounds__(256, 2) void joiner_hmma(
    const float* __restrict__ Wout, const float* __restrict__ bout,
    float* __restrict__ out)
{
    extern __shared__ __align__(16) char smem[];
    const uint32_t sb = smem_u32(smem);
    const int tid = threadIdx.x;
    const int wid = tid >> 5, lid = tid & 31;
    const int mg = wid;                 // 8 warps, 16 rows each
    const int q  = lid >> 2, qe = lid & 3;

    const int g  = blockIdx.y;
    const int t0 = (g & 3) * 128;
    const int bz = g >> 2;
    const int c  = blockIdx.x;                       // 0..17
    const int ustart = c * 24 + (c < 16 ? c : 16);
    const int ucnt   = 24 + (c < 16 ? 1 : 0);

    // ---- one-time: stage W*log2e (rows permuted), bias*log2e, sh tile ----
    for (int idx = tid; idx < V_ * H_; idx += 256) {
        const int n = idx / H_, k = idx - n * H_;
        *(__half*)(smem + S_BH + perm_phys(n) * PITCH + k * 2) =
            __float2half_rn(Wout[idx] * LOG2E);
    }
    if (tid < V_)
        ((float*)(smem + S_BIA))[perm_phys(tid)] = bout[tid] * LOG2E;
    {
        const uint4* src = (const uint4*)(g_shh + ((size_t)(bz * TPAD) + t0) * H_);
        for (int i = tid; i < 128 * 12; i += 256) {
            const int row = i / 12, kq = i - row * 12;
            *(uint4*)(smem + S_SHH + row * PITCH + kq * 16) = src[row * 12 + kq];
        }
    }

    // ldmatrix lane addresses
    const uint32_t aoff = (uint32_t)((lid & 15) * PITCH + (lid >> 4) * 16);
    const uint32_t boff = (uint32_t)(((lid & 7) + ((lid >> 4) << 3)) * PITCH + ((lid >> 3) & 1) * 16);
    const uint32_t sAh = sb + S_SHH + (uint32_t)(mg * 16 * PITCH) + aoff;
    const uint32_t sBh = sb + S_BH + boff;

    uint32_t* rbAll = (uint32_t*)(smem + S_RBH);     // [2][48] half2
    const float* biaL = (const float*)(smem + S_BIA) + 2 * qe;   // phys-indexed

    // prologue: rbh for first item into buffer 0
    if (tid < 48)
        rbAll[tid] = ((const uint32_t*)(g_rbhh + ((size_t)bz * U_ + ustart) * H_))[tid];

    int p = 0;
    for (int it = 0; it < ucnt; it++, p ^= 1) {
        const int u = ustart + it;

        __syncthreads();   // rbh buffer p ready (parked last iter) + tiles staged

        // prefetch next item's rbh (half2) into a register
        uint32_t nrb = 0u;
        if (tid < 48 && it + 1 < ucnt)
            nrb = ((const uint32_t*)(g_rbhh + ((size_t)bz * U_ + u + 1) * H_))[tid];

        const char* rbB = (const char*)(rbAll + p * 48);

        float acc[16][4];
        #pragma unroll
        for (int j = 0; j < 16; j++)
            #pragma unroll
            for (int e4 = 0; e4 < 4; e4++) acc[j][e4] = 0.0f;

        // ---- 6 k-steps: A = LDSM(sh) * rbh (HMUL2, 4/step), B = 8 LDSM4 ----
        #pragma unroll
        for (int s = 0; s < 6; s++) {
            uint32_t rb0 = *(const uint32_t*)(rbB + s * 32 + qe * 4);
            uint32_t rb1 = *(const uint32_t*)(rbB + s * 32 + 16 + qe * 4);
            uint32_t am[4], ah[4];
            LDSM4(am, sAh + s * 32);
            ah[0] = hmul2u(am[0], rb0);
            ah[1] = hmul2u(am[1], rb0);
            ah[2] = hmul2u(am[2], rb1);
            ah[3] = hmul2u(am[3], rb1);
            // two blocks of 4 B tiles to bound register liveness
            #pragma unroll
            for (int blk = 0; blk < 2; blk++) {
                uint32_t bq[4][4];
                #pragma unroll
                for (int jj = 0; jj < 4; jj++)
                    LDSM4(bq[jj], sBh + (blk * 4 + jj) * 16 * PITCH + s * 32);
                #pragma unroll
                for (int j8 = 0; j8 < 8; j8++)
                    MMA16816(acc[blk * 8 + j8], ah[0], ah[1], ah[2], ah[3],
                             bq[j8 >> 1][(j8 & 1) * 2], bq[j8 >> 1][(j8 & 1) * 2 + 1]);
            }
        }

        // park next rbh into the other buffer
        if (tid < 48 && it + 1 < ucnt) rbAll[(p ^ 1) * 48 + tid] = nrb;

        // ---- bias add (phys-indexed, log2-domain) ----
        #pragma unroll
        for (int j = 0; j < 16; j++) {
            float2 bv = *(const float2*)(biaL + 8 * j);
            acc[j][0] += bv.x; acc[j][1] += bv.y;
            acc[j][2] += bv.x; acc[j][3] += bv.y;
        }

        // ---- warp-local log2-softmax per row (h=0: row q, h=1: row q+8) ----
        #pragma unroll
        for (int h = 0; h < 2; h++) {
            float m = -3.4e38f;
            #pragma unroll
            for (int j = 0; j < 16; j++) {
                m = fmaxf(m, acc[j][2 * h]);
                m = fmaxf(m, acc[j][2 * h + 1]);
            }
            m = fmaxf(m, __shfl_xor_sync(0xffffffffu, m, 1));
            m = fmaxf(m, __shfl_xor_sync(0xffffffffu, m, 2));
            float ss = 0.0f;
            #pragma unroll
            for (int j = 0; j < 16; j++)
                ss += ex2f(acc[j][2 * h] - m) + ex2f(acc[j][2 * h + 1] - m);
            ss += __shfl_xor_sync(0xffffffffu, ss, 1);
            ss += __shfl_xor_sync(0xffffffffu, ss, 2);
            const float lsel = (m + __log2f(ss)) * LN2;   // lse in nat-log units

            const int t = t0 + mg * 16 + h * 8 + q;
            if (t >= T_) continue;
            float* orow = out + (((size_t)bz * T_ + t) * U_ + u) * V_ + 4 * qe;
            #pragma unroll
            for (int m2 = 0; m2 < 8; m2++) {
                float4 v;
                v.x = fmaf(acc[2 * m2][2 * h],     LN2, -lsel);
                v.y = fmaf(acc[2 * m2][2 * h + 1], LN2, -lsel);
                v.z = fmaf(acc[2 * m2 + 1][2 * h],     LN2, -lsel);
                v.w = fmaf(acc[2 * m2 + 1][2 * h + 1], LN2, -lsel);
                *(float4*)(orow + 16 * m2) = v;
            }
        }
    }
}

extern "C" void kernel_launch(void* const* d_in, const int* in_sizes, int n_in,
                              void* d_out, int out_size)
{
    (void)in_sizes; (void)n_in; (void)out_size;
    const float* s    = (const float*)d_in[0];
    const float* bmat = (const float*)d_in[1];
    const float* Wsh  = (const float*)d_in[2];
    const float* bsh  = (const float*)d_in[3];
    const float* Wbh  = (const float*)d_in[4];
    const float* bbh  = (const float*)d_in[5];
    const float* Wout = (const float*)d_in[6];
    const float* bout = (const float*)d_in[7];
    float* out = (float*)d_out;

    cudaFuncSetAttribute(joiner_hmma,
                         cudaFuncAttributeMaxDynamicSharedMemorySize, SMEM_MAIN);

    proj8<<<dim3((B_ * TPAD) / 8, 2), 96>>>(s, bmat, Wsh, bsh, Wbh, bbh);
    joiner_hmma<<<dim3(18, 16), 256, SMEM_MAIN>>>(Wout, bout, out);
}